// round 13
// baseline (speedup 1.0000x reference)
#include <cuda_runtime.h>

// Problem constants (fixed by dataset)
#define NIMG 8
#define NCLS 21
#define NCLS_PAD 22          // row 21 = trash row for IGNORE pixels
#define NPIX 262144          // 512*512 = 2^18
#define NDIM 32
#define IGNORE_LAB 255
#define PSHIFT 18

// Scratch (__device__ globals; finalize re-zeroes them each call; initial
// state is zero from static init -> every call starts from zeros)
__device__ float        g_sums[NIMG * NCLS * NDIM];
__device__ float        g_counts[NIMG * NCLS];
__device__ double       g_scal[5];     // 0:ce 1:validcnt 2:var 3:inter 4:sumsq
__device__ unsigned int g_ctr;

// ---------------------------------------------------------------------------
// Kernel 1: logit pass (unchanged — ~28us, near bandwidth roofline).
// ---------------------------------------------------------------------------
__global__ __launch_bounds__(256) void k_logit(const float* __restrict__ logit,
                                               const int* __restrict__ target) {
    int tid = blockIdx.x * blockDim.x + threadIdx.x;
    int stride = gridDim.x * blockDim.x;

    float ce = 0.f, cnt = 0.f, var = 0.f, inter = 0.f;

    for (int g = tid; g < NIMG * NPIX; g += stride) {
        int n = g >> PSHIFT;
        int p = g & (NPIX - 1);
        const float* lp = logit + (size_t)n * NCLS * NPIX + p;

        float v[NCLS];
#pragma unroll
        for (int c = 0; c < NCLS; c++) v[c] = __ldcs(lp + (size_t)c * NPIX);

        float m = v[0];
#pragma unroll
        for (int c = 1; c < NCLS; c++) m = fmaxf(m, v[c]);

        float s = 0.f, tot = 0.f;
#pragma unroll
        for (int c = 0; c < NCLS; c++) {
            s += __expf(v[c] - m);
            tot += v[c];
        }
        float lse = m + __logf(s);

        int lab = __ldg(target + g);
        if (lab != IGNORE_LAB) {
            float lg = v[0];
#pragma unroll
            for (int c = 1; c < NCLS; c++) lg = (c == lab) ? v[c] : lg;
            ce += (lse - lg);
            cnt += 1.f;
            var -= lg;
            inter += (tot - lg);
        }
    }

    int lane = threadIdx.x & 31;
    int wid = threadIdx.x >> 5;
#pragma unroll
    for (int o = 16; o > 0; o >>= 1) {
        ce += __shfl_down_sync(0xffffffffu, ce, o);
        cnt += __shfl_down_sync(0xffffffffu, cnt, o);
        var += __shfl_down_sync(0xffffffffu, var, o);
        inter += __shfl_down_sync(0xffffffffu, inter, o);
    }
    __shared__ float sred[4][8];
    if (lane == 0) {
        sred[0][wid] = ce; sred[1][wid] = cnt; sred[2][wid] = var; sred[3][wid] = inter;
    }
    __syncthreads();
    if (threadIdx.x == 0) {
        float a = 0, b = 0, c2 = 0, d2 = 0;
#pragma unroll
        for (int w = 0; w < 8; w++) {
            a += sred[0][w]; b += sred[1][w]; c2 += sred[2][w]; d2 += sred[3][w];
        }
        atomicAdd(&g_scal[0], (double)a);
        atomicAdd(&g_scal[1], (double)b);
        atomicAdd(&g_scal[2], (double)c2);
        atomicAdd(&g_scal[3], (double)d2);
    }
}

// ---------------------------------------------------------------------------
// Kernel 2: feature pass — R12 branchless body + SOFTWARE PIPELINE:
// iteration i+1's 8 loads (named scalars) issue before iteration i's
// accumulate chain, doubling in-flight loads per warp (MLP 8 -> 16) and
// overlapping the LDS/FFMA/STS chain with DRAM latency.
// ---------------------------------------------------------------------------
#define BLOCKS_PER_IMG 128
#define FEAT_GRID (BLOCKS_PER_IMG * NIMG)      // 1024
#define WARPS_PER_BLK 8
#define PIX_PER_WARP (NPIX / (BLOCKS_PER_IMG * WARPS_PER_BLK))   // 256

__global__ __launch_bounds__(256) void k_feat(const float* __restrict__ feat,
                                              const int* __restrict__ target,
                                              float* __restrict__ out) {
    __shared__ float acc[WARPS_PER_BLK][NCLS_PAD * NDIM];  // 22528 B
    __shared__ int   cshi[WARPS_PER_BLK][32];
    __shared__ float sq[WARPS_PER_BLK];
    __shared__ double dred[256];
    __shared__ bool is_last;

    const int lane = threadIdx.x & 31;
    const int wid = threadIdx.x >> 5;
    const int n = blockIdx.y;

    for (int idx = threadIdx.x; idx < WARPS_PER_BLK * NCLS_PAD * NDIM; idx += blockDim.x)
        (&acc[0][0])[idx] = 0.f;
    __syncthreads();

    const int p0 = (blockIdx.x * WARPS_PER_BLK + wid) * PIX_PER_WARP;
    const int* tg = target + (size_t)n * NPIX;
    const float* fp = feat + (size_t)n * NPIX * NDIM;

    float ssq = 0.f;
    int cntreg = 0;                 // lane c holds count of class c
    float* myacc = &acc[wid][0];

    // ---- prologue: load pixels p0..p0+3 ----
    int   l0 = __ldg(tg + p0 + 0), l1 = __ldg(tg + p0 + 1);
    int   l2 = __ldg(tg + p0 + 2), l3 = __ldg(tg + p0 + 3);
    float f0 = __ldcs(fp + (size_t)(p0 + 0) * NDIM + lane);
    float f1 = __ldcs(fp + (size_t)(p0 + 1) * NDIM + lane);
    float f2 = __ldcs(fp + (size_t)(p0 + 2) * NDIM + lane);
    float f3 = __ldcs(fp + (size_t)(p0 + 3) * NDIM + lane);

#pragma unroll 1
    for (int p = p0; p < p0 + PIX_PER_WARP - 4; p += 4) {
        const int q = p + 4;
        // ---- prefetch next iteration (named scalars; max addr p0+255) ----
        int   nl0 = __ldg(tg + q + 0), nl1 = __ldg(tg + q + 1);
        int   nl2 = __ldg(tg + q + 2), nl3 = __ldg(tg + q + 3);
        float nf0 = __ldcs(fp + (size_t)(q + 0) * NDIM + lane);
        float nf1 = __ldcs(fp + (size_t)(q + 1) * NDIM + lane);
        float nf2 = __ldcs(fp + (size_t)(q + 2) * NDIM + lane);
        float nf3 = __ldcs(fp + (size_t)(q + 3) * NDIM + lane);

        // ---- accumulate current (branchless trash-row form, proven) ----
        int  i0 = (l0 != IGNORE_LAB) ? l0 : NCLS;
        int  i1 = (l1 != IGNORE_LAB) ? l1 : NCLS;
        int  i2 = (l2 != IGNORE_LAB) ? l2 : NCLS;
        int  i3 = (l3 != IGNORE_LAB) ? l3 : NCLS;
        float m0 = (l0 != IGNORE_LAB) ? f0 : 0.f;
        float m1 = (l1 != IGNORE_LAB) ? f1 : 0.f;
        float m2 = (l2 != IGNORE_LAB) ? f2 : 0.f;
        float m3 = (l3 != IGNORE_LAB) ? f3 : 0.f;

        cntreg += (l0 == lane) ? 1 : 0;
        cntreg += (l1 == lane) ? 1 : 0;
        cntreg += (l2 == lane) ? 1 : 0;
        cntreg += (l3 == lane) ? 1 : 0;

        myacc[i0 * NDIM + lane] += m0; ssq += m0 * m0;
        myacc[i1 * NDIM + lane] += m1; ssq += m1 * m1;
        myacc[i2 * NDIM + lane] += m2; ssq += m2 * m2;
        myacc[i3 * NDIM + lane] += m3; ssq += m3 * m3;

        // ---- rotate ----
        l0 = nl0; l1 = nl1; l2 = nl2; l3 = nl3;
        f0 = nf0; f1 = nf1; f2 = nf2; f3 = nf3;
    }

    // ---- epilogue: accumulate final 4 pixels ----
    {
        int  i0 = (l0 != IGNORE_LAB) ? l0 : NCLS;
        int  i1 = (l1 != IGNORE_LAB) ? l1 : NCLS;
        int  i2 = (l2 != IGNORE_LAB) ? l2 : NCLS;
        int  i3 = (l3 != IGNORE_LAB) ? l3 : NCLS;
        float m0 = (l0 != IGNORE_LAB) ? f0 : 0.f;
        float m1 = (l1 != IGNORE_LAB) ? f1 : 0.f;
        float m2 = (l2 != IGNORE_LAB) ? f2 : 0.f;
        float m3 = (l3 != IGNORE_LAB) ? f3 : 0.f;

        cntreg += (l0 == lane) ? 1 : 0;
        cntreg += (l1 == lane) ? 1 : 0;
        cntreg += (l2 == lane) ? 1 : 0;
        cntreg += (l3 == lane) ? 1 : 0;

        myacc[i0 * NDIM + lane] += m0; ssq += m0 * m0;
        myacc[i1 * NDIM + lane] += m1; ssq += m1 * m1;
        myacc[i2 * NDIM + lane] += m2; ssq += m2 * m2;
        myacc[i3 * NDIM + lane] += m3; ssq += m3 * m3;
    }
    __syncthreads();

    // combine 8 warp buffers -> global partials (rows 0..20 only)
    for (int idx = threadIdx.x; idx < NCLS * NDIM; idx += blockDim.x) {
        float s = 0.f;
#pragma unroll
        for (int w = 0; w < WARPS_PER_BLK; w++) s += acc[w][idx];
        atomicAdd(&g_sums[(size_t)n * NCLS * NDIM + idx], s);
    }

    cshi[wid][lane] = cntreg;
#pragma unroll
    for (int o = 16; o > 0; o >>= 1) ssq += __shfl_down_sync(0xffffffffu, ssq, o);
    if (lane == 0) sq[wid] = ssq;
    __syncthreads();

    if (threadIdx.x < NCLS) {
        int s = 0;
#pragma unroll
        for (int w = 0; w < WARPS_PER_BLK; w++) s += cshi[w][threadIdx.x];
        atomicAdd(&g_counts[n * NCLS + threadIdx.x], (float)s);
    }
    if (threadIdx.x == 0) {
        float s = 0.f;
#pragma unroll
        for (int w = 0; w < WARPS_PER_BLK; w++) s += sq[w];
        atomicAdd(&g_scal[4], (double)s);
    }

    // ---------------- last-block finalize + re-zero ----------------------
    __threadfence();
    if (threadIdx.x == 0)
        is_last = (atomicAdd(&g_ctr, 1u) == FEAT_GRID - 1);
    __syncthreads();
    if (!is_last) return;
    __threadfence();   // acquire: all other blocks' atomics visible

    int tid = threadIdx.x;
    double center_neg = 0.0;
    for (int i = tid; i < NIMG * NCLS; i += 256) {
        double cntv = (double)__ldcg(&g_counts[i]);
        if (cntv > 0.0) {
            double m2 = 0.0;
            const float* s = &g_sums[(size_t)i * NDIM];
#pragma unroll
            for (int d = 0; d < NDIM; d++) {
                double sv = (double)__ldcg(s + d);
                m2 += sv * sv;
            }
            center_neg -= m2 / cntv;
        }
    }
    dred[tid] = center_neg;
    __syncthreads();
    for (int o = 128; o > 0; o >>= 1) {
        if (tid < o) dred[tid] += dred[tid + o];
        __syncthreads();
    }
    if (tid == 0) {
        double s0 = __ldcg(&g_scal[0]), s1 = __ldcg(&g_scal[1]);
        double s2 = __ldcg(&g_scal[2]), s3 = __ldcg(&g_scal[3]);
        double s4 = __ldcg(&g_scal[4]);
        double denom = s1 > 1.0 ? s1 : 1.0;
        double CE = s0 / denom;
        double VAR = s2 / (double)NPIX;
        double Inter = s3 / (double)NPIX;
        double Center = (s4 + dred[0]) / (double)NPIX;
        double loss = (CE + 1.0 * VAR + 0.5 * Inter + 0.1 * Center) / (double)NIMG;
        out[0] = (float)loss;
    }
    __syncthreads();   // all scratch reads complete before re-zero

    for (int i = tid; i < NIMG * NCLS * NDIM; i += 256) g_sums[i] = 0.f;
    if (tid < NIMG * NCLS) g_counts[tid] = 0.f;
    if (tid < 5) g_scal[tid] = 0.0;
    if (tid == 0) g_ctr = 0u;
}

// ---------------------------------------------------------------------------
extern "C" void kernel_launch(void* const* d_in, const int* in_sizes, int n_in,
                              void* d_out, int out_size) {
    const float* logit = (const float*)d_in[0];
    const int* target = (const int*)d_in[1];
    const float* feat = (const float*)d_in[2];
    float* out = (float*)d_out;

    k_logit<<<1184, 256>>>(logit, target);
    k_feat<<<dim3(BLOCKS_PER_IMG, NIMG), 256>>>(feat, target, out);
}

// round 14
// speedup vs baseline: 1.2716x; 1.2716x over previous
#include <cuda_runtime.h>
#include <cstdint>

// Problem constants (fixed by dataset)
#define NIMG 8
#define NCLS 21
#define NCLS_PAD 22          // row 21 = trash row for IGNORE pixels
#define NPIX 262144          // 512*512 = 2^18
#define NDIM 32
#define IGNORE_LAB 255
#define PSHIFT 18

// Scratch (__device__ globals; finalize re-zeroes them each call; initial
// state is zero from static init -> every call starts from zeros)
__device__ float        g_sums[NIMG * NCLS * NDIM];
__device__ float        g_counts[NIMG * NCLS];
__device__ double       g_scal[5];     // 0:ce 1:validcnt 2:var 3:inter 4:sumsq
__device__ unsigned int g_ctr;

// ---- cp.async helpers ------------------------------------------------------
__device__ __forceinline__ void cpa16(uint32_t smem_dst, const void* gmem_src) {
    asm volatile("cp.async.cg.shared.global [%0], [%1], 16;"
                 :: "r"(smem_dst), "l"(gmem_src));
}
__device__ __forceinline__ void cpa_commit() {
    asm volatile("cp.async.commit_group;");
}
template <int N>
__device__ __forceinline__ void cpa_wait() {
    asm volatile("cp.async.wait_group %0;" :: "n"(N));
}

// ---------------------------------------------------------------------------
// Kernel 1: logit pass (unchanged — ~28us, near bandwidth roofline).
// ---------------------------------------------------------------------------
__global__ __launch_bounds__(256) void k_logit(const float* __restrict__ logit,
                                               const int* __restrict__ target) {
    int tid = blockIdx.x * blockDim.x + threadIdx.x;
    int stride = gridDim.x * blockDim.x;

    float ce = 0.f, cnt = 0.f, var = 0.f, inter = 0.f;

    for (int g = tid; g < NIMG * NPIX; g += stride) {
        int n = g >> PSHIFT;
        int p = g & (NPIX - 1);
        const float* lp = logit + (size_t)n * NCLS * NPIX + p;

        float v[NCLS];
#pragma unroll
        for (int c = 0; c < NCLS; c++) v[c] = __ldcs(lp + (size_t)c * NPIX);

        float m = v[0];
#pragma unroll
        for (int c = 1; c < NCLS; c++) m = fmaxf(m, v[c]);

        float s = 0.f, tot = 0.f;
#pragma unroll
        for (int c = 0; c < NCLS; c++) {
            s += __expf(v[c] - m);
            tot += v[c];
        }
        float lse = m + __logf(s);

        int lab = __ldg(target + g);
        if (lab != IGNORE_LAB) {
            float lg = v[0];
#pragma unroll
            for (int c = 1; c < NCLS; c++) lg = (c == lab) ? v[c] : lg;
            ce += (lse - lg);
            cnt += 1.f;
            var -= lg;
            inter += (tot - lg);
        }
    }

    int lane = threadIdx.x & 31;
    int wid = threadIdx.x >> 5;
#pragma unroll
    for (int o = 16; o > 0; o >>= 1) {
        ce += __shfl_down_sync(0xffffffffu, ce, o);
        cnt += __shfl_down_sync(0xffffffffu, cnt, o);
        var += __shfl_down_sync(0xffffffffu, var, o);
        inter += __shfl_down_sync(0xffffffffu, inter, o);
    }
    __shared__ float sred[4][8];
    if (lane == 0) {
        sred[0][wid] = ce; sred[1][wid] = cnt; sred[2][wid] = var; sred[3][wid] = inter;
    }
    __syncthreads();
    if (threadIdx.x == 0) {
        float a = 0, b = 0, c2 = 0, d2 = 0;
#pragma unroll
        for (int w = 0; w < 8; w++) {
            a += sred[0][w]; b += sred[1][w]; c2 += sred[2][w]; d2 += sred[3][w];
        }
        atomicAdd(&g_scal[0], (double)a);
        atomicAdd(&g_scal[1], (double)b);
        atomicAdd(&g_scal[2], (double)c2);
        atomicAdd(&g_scal[3], (double)d2);
    }
}

// ---------------------------------------------------------------------------
// Kernel 2: feature pass — cp.async DECOUPLED pipeline.
//   - 4-stage smem ring per warp: one LDGSTS stages 4 pixels (512B contig)
//   - labels staged once per chunk (1KB/warp), LDS.128 broadcast in loop
//   - consume chain reads smem (29cyc), DRAM latency absorbed by ring depth
//   - accumulate body = proven R12 branchless trash-row form
// Plus last-block finalize + scratch re-zero (proven).
// ---------------------------------------------------------------------------
#define BLOCKS_PER_IMG 128
#define FEAT_GRID (BLOCKS_PER_IMG * NIMG)      // 1024
#define WARPS_PER_BLK 8
#define PIX_PER_WARP 256
#define NGROUPS 64                              // 4 pixels per group
#define NSTAGE 4

__global__ __launch_bounds__(256) void k_feat(const float* __restrict__ feat,
                                              const int* __restrict__ target,
                                              float* __restrict__ out) {
    __shared__ float acc[WARPS_PER_BLK][NCLS_PAD * NDIM];       // 22528 B
    __shared__ float sbuf[WARPS_PER_BLK][NSTAGE][4 * NDIM];     // 16384 B
    __shared__ int   slab[WARPS_PER_BLK][PIX_PER_WARP];         // 8192 B
    __shared__ int   cshi[WARPS_PER_BLK][32];
    __shared__ float sq[WARPS_PER_BLK];
    __shared__ double dred[256];
    __shared__ bool is_last;

    const int lane = threadIdx.x & 31;
    const int wid = threadIdx.x >> 5;
    const int n = blockIdx.y;

    for (int idx = threadIdx.x; idx < WARPS_PER_BLK * NCLS_PAD * NDIM; idx += blockDim.x)
        (&acc[0][0])[idx] = 0.f;
    __syncthreads();

    const int p0 = (blockIdx.x * WARPS_PER_BLK + wid) * PIX_PER_WARP;
    const int* tg = target + (size_t)n * NPIX;
    const char* fbase = (const char*)(feat + ((size_t)n * NPIX + p0) * NDIM);

    const uint32_t slab_s = (uint32_t)__cvta_generic_to_shared(&slab[wid][0]);
    const uint32_t sbuf_s = (uint32_t)__cvta_generic_to_shared(&sbuf[wid][0][0]);
    const uint32_t loff = (uint32_t)lane * 16u;

    // ---- prologue: stage labels (1KB) + first 3 feature groups ----
    // commit group 0: labels + feature group 0
    cpa16(slab_s + loff,        (const char*)(tg + p0) + loff);
    cpa16(slab_s + 512 + loff,  (const char*)(tg + p0) + 512 + loff);
    cpa16(sbuf_s + 0 * 512 + loff, fbase + (size_t)0 * 512 + loff);
    cpa_commit();
    cpa16(sbuf_s + 1 * 512 + loff, fbase + (size_t)1 * 512 + loff);
    cpa_commit();
    cpa16(sbuf_s + 2 * 512 + loff, fbase + (size_t)2 * 512 + loff);
    cpa_commit();

    float ssq = 0.f;
    int cntreg = 0;                 // lane c holds count of class c
    float* myacc = &acc[wid][0];

#pragma unroll 1
    for (int g = 0; g < NGROUPS; g++) {
        cpa_wait<2>();              // group g (and labels) complete
        __syncwarp();               // cross-lane visibility of staged bytes

        const int slot = g & (NSTAGE - 1);
        const float* sf = &sbuf[wid][slot][0];

        // 4 labels via single broadcast LDS.128
        int4 lv = *(const int4*)&slab[wid][g * 4];
        int l0 = lv.x, l1 = lv.y, l2 = lv.z, l3 = lv.w;

        // 4 named scalar smem loads (29cyc latency, fully pipelined)
        float f0 = sf[0 * NDIM + lane];
        float f1 = sf[1 * NDIM + lane];
        float f2 = sf[2 * NDIM + lane];
        float f3 = sf[3 * NDIM + lane];

        // issue next stage before consuming (keeps ring full)
        if (g < NGROUPS - 3) {
            const int ns = (g + 3) & (NSTAGE - 1);
            cpa16(sbuf_s + (uint32_t)ns * 512 + loff,
                  fbase + (size_t)(g + 3) * 512 + loff);
        }
        cpa_commit();               // empty groups keep wait accounting simple

        // ---- branchless accumulate (proven R12 form) ----
        int  i0 = (l0 != IGNORE_LAB) ? l0 : NCLS;
        int  i1 = (l1 != IGNORE_LAB) ? l1 : NCLS;
        int  i2 = (l2 != IGNORE_LAB) ? l2 : NCLS;
        int  i3 = (l3 != IGNORE_LAB) ? l3 : NCLS;
        float m0 = (l0 != IGNORE_LAB) ? f0 : 0.f;
        float m1 = (l1 != IGNORE_LAB) ? f1 : 0.f;
        float m2 = (l2 != IGNORE_LAB) ? f2 : 0.f;
        float m3 = (l3 != IGNORE_LAB) ? f3 : 0.f;

        cntreg += (l0 == lane) ? 1 : 0;
        cntreg += (l1 == lane) ? 1 : 0;
        cntreg += (l2 == lane) ? 1 : 0;
        cntreg += (l3 == lane) ? 1 : 0;

        myacc[i0 * NDIM + lane] += m0; ssq += m0 * m0;
        myacc[i1 * NDIM + lane] += m1; ssq += m1 * m1;
        myacc[i2 * NDIM + lane] += m2; ssq += m2 * m2;
        myacc[i3 * NDIM + lane] += m3; ssq += m3 * m3;
    }
    __syncthreads();

    // combine 8 warp buffers -> global partials (rows 0..20 only)
    for (int idx = threadIdx.x; idx < NCLS * NDIM; idx += blockDim.x) {
        float s = 0.f;
#pragma unroll
        for (int w = 0; w < WARPS_PER_BLK; w++) s += acc[w][idx];
        atomicAdd(&g_sums[(size_t)n * NCLS * NDIM + idx], s);
    }

    cshi[wid][lane] = cntreg;
#pragma unroll
    for (int o = 16; o > 0; o >>= 1) ssq += __shfl_down_sync(0xffffffffu, ssq, o);
    if (lane == 0) sq[wid] = ssq;
    __syncthreads();

    if (threadIdx.x < NCLS) {
        int s = 0;
#pragma unroll
        for (int w = 0; w < WARPS_PER_BLK; w++) s += cshi[w][threadIdx.x];
        atomicAdd(&g_counts[n * NCLS + threadIdx.x], (float)s);
    }
    if (threadIdx.x == 0) {
        float s = 0.f;
#pragma unroll
        for (int w = 0; w < WARPS_PER_BLK; w++) s += sq[w];
        atomicAdd(&g_scal[4], (double)s);
    }

    // ---------------- last-block finalize + re-zero ----------------------
    __threadfence();
    if (threadIdx.x == 0)
        is_last = (atomicAdd(&g_ctr, 1u) == FEAT_GRID - 1);
    __syncthreads();
    if (!is_last) return;
    __threadfence();   // acquire: all other blocks' atomics visible

    int tid = threadIdx.x;
    double center_neg = 0.0;
    for (int i = tid; i < NIMG * NCLS; i += 256) {
        double cntv = (double)__ldcg(&g_counts[i]);
        if (cntv > 0.0) {
            double m2 = 0.0;
            const float* s = &g_sums[(size_t)i * NDIM];
#pragma unroll
            for (int d = 0; d < NDIM; d++) {
                double sv = (double)__ldcg(s + d);
                m2 += sv * sv;
            }
            center_neg -= m2 / cntv;
        }
    }
    dred[tid] = center_neg;
    __syncthreads();
    for (int o = 128; o > 0; o >>= 1) {
        if (tid < o) dred[tid] += dred[tid + o];
        __syncthreads();
    }
    if (tid == 0) {
        double s0 = __ldcg(&g_scal[0]), s1 = __ldcg(&g_scal[1]);
        double s2 = __ldcg(&g_scal[2]), s3 = __ldcg(&g_scal[3]);
        double s4 = __ldcg(&g_scal[4]);
        double denom = s1 > 1.0 ? s1 : 1.0;
        double CE = s0 / denom;
        double VAR = s2 / (double)NPIX;
        double Inter = s3 / (double)NPIX;
        double Center = (s4 + dred[0]) / (double)NPIX;
        double loss = (CE + 1.0 * VAR + 0.5 * Inter + 0.1 * Center) / (double)NIMG;
        out[0] = (float)loss;
    }
    __syncthreads();   // all scratch reads complete before re-zero

    for (int i = tid; i < NIMG * NCLS * NDIM; i += 256) g_sums[i] = 0.f;
    if (tid < NIMG * NCLS) g_counts[tid] = 0.f;
    if (tid < 5) g_scal[tid] = 0.0;
    if (tid == 0) g_ctr = 0u;
}

// ---------------------------------------------------------------------------
extern "C" void kernel_launch(void* const* d_in, const int* in_sizes, int n_in,
                              void* d_out, int out_size) {
    const float* logit = (const float*)d_in[0];
    const int* target = (const int*)d_in[1];
    const float* feat = (const float*)d_in[2];
    float* out = (float*)d_out;

    k_logit<<<1184, 256>>>(logit, target);
    k_feat<<<dim3(BLOCKS_PER_IMG, NIMG), 256>>>(feat, target, out);
}